// round 16
// baseline (speedup 1.0000x reference)
#include <cuda_runtime.h>
#include <cstdint>

// PatchPooling: out[b,p,d] = mean over s in [fr, to) of batch[b,s,d]; empty -> -1
// B=64, S=1024, D=256, P=64. patch_lengths in [0,16).
//
// Two-kernel plan (both graph-capturable, no allocations):
//  1) scan_kernel: per-batch exclusive cumsum of patch_lengths -> g_cum[B][P+1]
//  2) pool_kernel: one 256-thread block per (b,p). 4 row-groups x 64 d4-lanes;
//     each thread does <=4 independent float4 loads (rows g, g+4, g+8, g+12),
//     partial sums reduced via shared memory.

#define PP_S 1024
#define PP_D 256
#define PP_P 64
#define PP_B_MAX 64
#define PP_D4 (PP_D / 4)          // 64 float4 per row
#define ROW_GROUPS 4

__device__ int g_cum[PP_B_MAX * (PP_P + 1)];

__global__ void scan_kernel(const int* __restrict__ plen, int B)
{
    const int b   = blockIdx.x;
    const int lid = threadIdx.x;          // 0..31
    int a = plen[b * PP_P + lid];         // lengths [0..31]
    int c = plen[b * PP_P + 32 + lid];    // lengths [32..63]
    #pragma unroll
    for (int o = 1; o < 32; o <<= 1) {
        int ta = __shfl_up_sync(0xffffffffu, a, o);
        int tc = __shfl_up_sync(0xffffffffu, c, o);
        if (lid >= o) { a += ta; c += tc; }
    }
    c += __shfl_sync(0xffffffffu, a, 31);
    int* cum = g_cum + b * (PP_P + 1);
    cum[lid + 1]  = a;
    cum[lid + 33] = c;
    if (lid == 0) cum[0] = 0;
}

__global__ __launch_bounds__(256)
void pool_kernel(const float4* __restrict__ batch,
                 float4* __restrict__ out, int B)
{
    const int p   = blockIdx.x;            // 0..63
    const int b   = blockIdx.y;            // 0..B-1
    const int tid = threadIdx.x;
    const int g    = tid >> 6;             // row group 0..3
    const int lane = tid & 63;             // float4 column of D

    const int* cum = g_cum + b * (PP_P + 1);
    int fr = cum[p];
    int to = cum[p + 1];
    fr = fr < PP_S ? fr : PP_S;            // defensive clamp
    to = to < PP_S ? to : PP_S;
    const int cnt = to - fr;

    const float4* rowp = batch + (size_t)b * PP_S * PP_D4
                               + (size_t)fr * PP_D4 + lane;

    // Up to 4 independent loads per thread: rows g, g+4, g+8, g+12.
    float ax = 0.f, ay = 0.f, az = 0.f, aw = 0.f;
    #pragma unroll
    for (int k = 0; k < 4; k++) {
        const int i = g + k * ROW_GROUPS;
        if (i < cnt) {
            float4 v = rowp[(size_t)i * PP_D4];
            ax += v.x; ay += v.y; az += v.z; aw += v.w;
        }
    }
    // Defensive tail (cannot trigger with lengths <= 15).
    for (int i = g + 16; i < cnt; i += ROW_GROUPS) {
        float4 v = rowp[(size_t)i * PP_D4];
        ax += v.x; ay += v.y; az += v.z; aw += v.w;
    }

    __shared__ float4 s_part[ROW_GROUPS][PP_D4];
    s_part[g][lane] = make_float4(ax, ay, az, aw);
    __syncthreads();

    if (g == 0) {
        float4 p1 = s_part[1][lane];
        float4 p2 = s_part[2][lane];
        float4 p3 = s_part[3][lane];
        ax += p1.x + p2.x + p3.x;
        ay += p1.y + p2.y + p3.y;
        az += p1.z + p2.z + p3.z;
        aw += p1.w + p2.w + p3.w;

        float4 o;
        if (cnt == 0) {
            o.x = o.y = o.z = o.w = -1.0f;
        } else {
            const float inv = 1.0f / (float)cnt;
            o.x = ax * inv; o.y = ay * inv; o.z = az * inv; o.w = aw * inv;
        }
        out[((size_t)b * PP_P + p) * PP_D4 + lane] = o;
    }
}

extern "C" void kernel_launch(void* const* d_in, const int* in_sizes, int n_in,
                              void* d_out, int out_size)
{
    const float4* batch = (const float4*)d_in[0];       // [B,S,D] fp32
    const int*    plen  = (const int*)d_in[1];          // [B,P] int32
    float4*       out   = (float4*)d_out;               // [B,P,D] fp32

    const int B = in_sizes[1] / PP_P;                   // 64

    scan_kernel<<<B, 32>>>(plen, B);
    dim3 grid(PP_P, B);                                 // (64, 64) = 4096 blocks
    pool_kernel<<<grid, 256>>>(batch, out, B);
}

// round 17
// speedup vs baseline: 1.0459x; 1.0459x over previous
#include <cuda_runtime.h>
#include <cstdint>

// PatchPooling: out[b,p,d] = mean over s in [fr, to) of batch[b,s,d]; empty -> -1
// B=64, S=1024, D=256, P=64. patch_lengths in [0,16).
//
// One block = 4 consecutive patches of one batch (a contiguous row range of
// <= 60 rows). The block issues ONE cp.async.bulk (global->shared, mbarrier
// completion) for the whole range -- the bulk-copy engine provides the MLP
// that LDG scheduling never achieved -- then reduces from smem (LDS.128,
// conflict-free) and writes the 4 output rows.

#define PP_S 1024
#define PP_D 256
#define PP_P 64
#define PP_D4 (PP_D / 4)              // 64 float4 per row
#define QUAD 4
#define MAX_LEN 15                    // randint(0,16) -> lengths <= 15
#define BUF_ROWS (QUAD * MAX_LEN)     // 60
#define ROW_BYTES (PP_D * 4)          // 1024
#define BUF_BYTES (BUF_ROWS * ROW_BYTES)  // 61440

__device__ __forceinline__ uint32_t smem_u32(const void* p) {
    uint32_t a;
    asm("{ .reg .u64 t; cvta.to.shared.u64 t, %1; cvt.u32.u64 %0, t; }"
        : "=r"(a) : "l"(p));
    return a;
}

__device__ __forceinline__ void mbar_init(uint32_t bar, uint32_t cnt) {
    asm volatile("mbarrier.init.shared.b64 [%0], %1;" :: "r"(bar), "r"(cnt) : "memory");
}
__device__ __forceinline__ void mbar_expect_tx(uint32_t bar, uint32_t bytes) {
    asm volatile("mbarrier.arrive.expect_tx.shared.b64 _, [%0], %1;"
                 :: "r"(bar), "r"(bytes) : "memory");
}
__device__ __forceinline__ void mbar_wait(uint32_t bar, uint32_t parity) {
    asm volatile(
        "{\n\t"
        ".reg .pred P;\n\t"
        "LW%=:\n\t"
        "mbarrier.try_wait.parity.acquire.cta.shared::cta.b64 P, [%0], %1, 0x989680;\n\t"
        "@P bra LD%=;\n\t"
        "bra LW%=;\n\t"
        "LD%=:\n\t"
        "}"
        :: "r"(bar), "r"(parity) : "memory");
}
__device__ __forceinline__ void bulk_copy_g2s(uint32_t smem_dst, const void* gsrc,
                                              uint32_t bytes, uint32_t bar) {
    asm volatile(
        "cp.async.bulk.shared::cluster.global.mbarrier::complete_tx::bytes "
        "[%0], [%1], %2, [%3];"
        :: "r"(smem_dst), "l"(gsrc), "r"(bytes), "r"(bar) : "memory");
}

__global__ __launch_bounds__(256)
void pool_tma_kernel(const float4* __restrict__ batch,
                     const int* __restrict__ plen,
                     float4* __restrict__ out)
{
    extern __shared__ float4 s_buf[];                 // BUF_ROWS * PP_D4
    __shared__ int s_cum[PP_P + 1];
    __shared__ __align__(8) unsigned long long s_bar;

    const int b   = blockIdx.y;                       // batch
    const int pq  = blockIdx.x;                       // patch quad 0..15
    const int tid = threadIdx.x;
    const uint32_t bar = smem_u32(&s_bar);

    // Warp-0 shfl scan of the 64 lengths -> exclusive cumsum s_cum[0..64].
    if (tid < 32) {
        int a = plen[b * PP_P + tid];
        int c = plen[b * PP_P + 32 + tid];
        #pragma unroll
        for (int o = 1; o < 32; o <<= 1) {
            int ta = __shfl_up_sync(0xffffffffu, a, o);
            int tc = __shfl_up_sync(0xffffffffu, c, o);
            if (tid >= o) { a += ta; c += tc; }
        }
        c += __shfl_sync(0xffffffffu, a, 31);
        s_cum[tid + 1]  = a;
        s_cum[tid + 33] = c;
        if (tid == 0) s_cum[0] = 0;
    }
    if (tid == 0) {
        mbar_init(bar, 1);
        asm volatile("fence.proxy.async.shared::cta;" ::: "memory");
    }
    __syncthreads();

    const int p0  = pq * QUAD;
    int frq = s_cum[p0];       frq = frq < PP_S ? frq : PP_S;
    int toq = s_cum[p0 + QUAD]; toq = toq < PP_S ? toq : PP_S;
    const int rows = toq - frq;
    const bool fits = (rows <= BUF_ROWS);             // always true for this dataset
    const uint32_t bytes = fits ? (uint32_t)rows * ROW_BYTES : 0u;

    const float4* gbase = batch + ((size_t)b * PP_S + frq) * PP_D4;

    if (tid == 0 && bytes > 0) {
        mbar_expect_tx(bar, bytes);
        bulk_copy_g2s(smem_u32(s_buf), gbase, bytes, bar);
    }
    if (bytes > 0) mbar_wait(bar, 0);

    const int slice = tid >> 6;                       // patch within quad
    const int lane  = tid & 63;                       // float4 column of D
    const int p     = p0 + slice;

    int fr = s_cum[p];     fr = fr < PP_S ? fr : PP_S;
    int to = s_cum[p + 1]; to = to < PP_S ? to : PP_S;
    const int cnt = to - fr;

    float ax = 0.f, ay = 0.f, az = 0.f, aw = 0.f;
    if (fits) {
        const float4* rp = s_buf + (size_t)(fr - frq) * PP_D4 + lane;
        #pragma unroll
        for (int i = 0; i < MAX_LEN; i++) {
            if (i < cnt) {
                float4 v = rp[(size_t)i * PP_D4];     // LDS.128, conflict-free
                ax += v.x; ay += v.y; az += v.z; aw += v.w;
            }
        }
    } else {
        // Defensive fallback (lengths > 15 cannot occur with this dataset).
        const float4* rp = batch + ((size_t)b * PP_S + fr) * PP_D4 + lane;
        for (int i = 0; i < cnt; i++) {
            float4 v = rp[(size_t)i * PP_D4];
            ax += v.x; ay += v.y; az += v.z; aw += v.w;
        }
    }

    float4 o;
    if (cnt == 0) {
        o.x = o.y = o.z = o.w = -1.0f;
    } else {
        const float inv = 1.0f / (float)cnt;
        o.x = ax * inv; o.y = ay * inv; o.z = az * inv; o.w = aw * inv;
    }
    out[((size_t)b * PP_P + p) * PP_D4 + lane] = o;
}

extern "C" void kernel_launch(void* const* d_in, const int* in_sizes, int n_in,
                              void* d_out, int out_size)
{
    const float4* batch = (const float4*)d_in[0];     // [B,S,D] fp32
    const int*    plen  = (const int*)d_in[1];        // [B,P] int32
    float4*       out   = (float4*)d_out;             // [B,P,D] fp32

    const int B = in_sizes[1] / PP_P;                 // 64

    static int smem_set = 0;
    if (!smem_set) {
        cudaFuncSetAttribute(pool_tma_kernel,
                             cudaFuncAttributeMaxDynamicSharedMemorySize,
                             BUF_BYTES);
        smem_set = 1;
    }

    dim3 grid(PP_P / QUAD, B);                        // (16, 64) = 1024 blocks
    pool_tma_kernel<<<grid, 256, BUF_BYTES>>>(batch, plen, out);
}